// round 3
// baseline (speedup 1.0000x reference)
#include <cuda_runtime.h>
#include <cuda_bf16.h>

#define BINS 32
#define CZ   128
#define NCLS 66            // 2*BINS + 2
#define LSEQ 768
#define NB   2
#define TPB  512

// One block per (b, i) row. 16 warps/block; each warp covers j = warp + 16*t
// (32 lanes x float4 = 128 floats = one C_Z vector per j). Loop unrolled x4
// for independent LDS->STG chains (store MLP).
__global__ __launch_bounds__(TPB) void relpos_kernel(
    const int*   __restrict__ ridx,   // [B, L] int32
    const int*   __restrict__ rmask,  // [B, L] bool widened to int32
    const float* __restrict__ W,      // [66, 128]
    const float* __restrict__ bias,   // [128]
    float*       __restrict__ out)    // [B, L, L, 128]
{
    __shared__ float wb[NCLS * CZ];   // W + b, 33792 B
    __shared__ int   rj[LSEQ];
    __shared__ float mj[LSEQ];        // mask as float (0/1)

    const int tid = threadIdx.x;

    // Build Wb = W + b cooperatively
    #pragma unroll 4
    for (int k = tid; k < NCLS * CZ; k += TPB)
        wb[k] = W[k] + bias[k & (CZ - 1)];

    const int row = blockIdx.x;        // 0 .. B*L-1
    const int b   = row / LSEQ;
    // cache this batch's residue row + mask row
    for (int k = tid; k < LSEQ; k += TPB) {
        rj[k] = ridx[b * LSEQ + k];
        mj[k] = (rmask[b * LSEQ + k] != 0) ? 1.0f : 0.0f;
    }
    __syncthreads();

    const int   i    = row - b * LSEQ;
    const int   ri   = rj[i];
    const float mi   = mj[i];
    const int   lane = tid & 31;
    const int   warp = tid >> 5;
    const int   NW   = TPB / 32;       // 16 warps

    float4* orow = reinterpret_cast<float4*>(out) + (size_t)row * LSEQ * (CZ / 4);

    // 768 / 16 = 48 iterations per warp; unroll 4 for store ILP
    #pragma unroll 4
    for (int j = warp; j < LSEQ; j += NW) {
        int d = rj[j] - ri;                         // diff[b,i,j] = r[j] - r[i]
        d = min(max(d, -BINS), BINS) + BINS + 1;    // class index in [1, 65]
        float  m = mi * mj[j];
        float4 v = *reinterpret_cast<const float4*>(&wb[d * CZ + lane * 4]);
        v.x *= m; v.y *= m; v.z *= m; v.w *= m;
        __stcs(&orow[(size_t)j * (CZ / 4) + lane], v);
    }
}

extern "C" void kernel_launch(void* const* d_in, const int* in_sizes, int n_in,
                              void* d_out, int out_size) {
    const int*   ridx  = (const int*)d_in[0];
    const int*   rmask = (const int*)d_in[1];
    const float* W     = (const float*)d_in[2];
    const float* bias  = (const float*)d_in[3];
    float*       out   = (float*)d_out;

    relpos_kernel<<<NB * LSEQ, TPB>>>(ridx, rmask, W, bias, out);
}

// round 4
// speedup vs baseline: 1.0737x; 1.0737x over previous
#include <cuda_runtime.h>
#include <cuda_bf16.h>

#define BINS 32
#define CZ   128
#define NCLS 66            // 2*BINS + 2
#define LSEQ 768
#define NB   2
#define TPB  256

// One block per (b, i) row. 8 warps/block, each warp handles one j per
// iteration (32 lanes x float4 = 128 floats = one C_Z vector).
// Default (write-back) stores: let the 126MB L2 write-combine the 604MB
// output stream for better DRAM burst efficiency.
__global__ __launch_bounds__(TPB) void relpos_kernel(
    const int*   __restrict__ ridx,   // [B, L] int32
    const int*   __restrict__ rmask,  // [B, L] bool widened to int32
    const float* __restrict__ W,      // [66, 128]
    const float* __restrict__ bias,   // [128]
    float*       __restrict__ out)    // [B, L, L, 128]
{
    __shared__ float wb[NCLS * CZ];   // W + b, 33792 B
    __shared__ int   rj[LSEQ];
    __shared__ int   mj[LSEQ];

    const int tid = threadIdx.x;

    // Build Wb = W + b cooperatively
    #pragma unroll 4
    for (int k = tid; k < NCLS * CZ; k += TPB)
        wb[k] = W[k] + bias[k & (CZ - 1)];

    const int row = blockIdx.x;        // 0 .. B*L-1
    const int b   = row / LSEQ;
    // cache this batch's residue row + mask row
    for (int k = tid; k < LSEQ; k += TPB) {
        rj[k] = ridx[b * LSEQ + k];
        mj[k] = rmask[b * LSEQ + k];
    }
    __syncthreads();

    const int  i    = row - b * LSEQ;
    const int  ri   = rj[i];
    const bool mi   = (mj[i] != 0);
    const int  lane = tid & 31;
    const int  warp = tid >> 5;

    float4* orow = reinterpret_cast<float4*>(out) + (size_t)row * LSEQ * (CZ / 4);

    #pragma unroll 2
    for (int j = warp; j < LSEQ; j += TPB / 32) {
        int d = rj[j] - ri;                         // diff[b,i,j] = r[j] - r[i]
        d = min(max(d, -BINS), BINS) + BINS + 1;    // class index in [1, 65]
        float4 v = *reinterpret_cast<const float4*>(&wb[d * CZ + lane * 4]);
        if (!(mi && (mj[j] != 0))) v = make_float4(0.f, 0.f, 0.f, 0.f);
        orow[(size_t)j * (CZ / 4) + lane] = v;
    }
}

extern "C" void kernel_launch(void* const* d_in, const int* in_sizes, int n_in,
                              void* d_out, int out_size) {
    const int*   ridx  = (const int*)d_in[0];
    const int*   rmask = (const int*)d_in[1];
    const float* W     = (const float*)d_in[2];
    const float* bias  = (const float*)d_in[3];
    float*       out   = (float*)d_out;

    relpos_kernel<<<NB * LSEQ, TPB>>>(ridx, rmask, W, bias, out);
}

// round 5
// speedup vs baseline: 1.2695x; 1.1824x over previous
#include <cuda_runtime.h>
#include <cuda_bf16.h>

#define BINS 32
#define CZ   128
#define NCLS 66              // 2*BINS + 2
#define LSEQ 768
#define NB   2
#define TPB  256
#define NCTAS (148 * 5)      // persistent grid: 5 CTAs/SM x 148 SMs
#define JCHUNK 96            // j-vectors per work chunk
#define NCHUNK (NB * LSEQ * (LSEQ / JCHUNK))   // 12288

// Persistent-CTA version. Each CTA builds the Wb=W+b table (with row 0 zeroed
// as the "masked" class) and caches residue/mask rows for BOTH batches, then
// grid-strides over 12288 (row, j-block) chunks. Each warp stores one C_Z=128
// float vector per iteration as 2x LDS.128 -> 2x STG.E.128 (.cs streaming).
__global__ __launch_bounds__(TPB) void relpos_kernel(
    const int*   __restrict__ ridx,   // [B, L] int32
    const int*   __restrict__ rmask,  // [B, L] bool widened to int32
    const float* __restrict__ W,      // [66, 128]
    const float* __restrict__ bias,   // [128]
    float*       __restrict__ out)    // [B, L, L, 128]
{
    __shared__ float         wb[NCLS * CZ];    // 33792 B; row 0 = zeros
    __shared__ int           rj[NB * LSEQ];    // 6144 B
    __shared__ unsigned char mj[NB * LSEQ];    // 1536 B

    const int tid = threadIdx.x;

    // Wb table: row 0 (unused by valid classes, idx in [1,65]) = zeros -> mask sink
    #pragma unroll 4
    for (int k = tid; k < NCLS * CZ; k += TPB)
        wb[k] = (k < CZ) ? 0.0f : (W[k] + bias[k & (CZ - 1)]);

    for (int k = tid; k < NB * LSEQ; k += TPB) {
        rj[k] = ridx[k];
        mj[k] = (unsigned char)(rmask[k] != 0);
    }
    __syncthreads();

    const int lane = tid & 31;
    const int warp = tid >> 5;

    for (int c = blockIdx.x; c < NCHUNK; c += NCTAS) {
        const int row   = c >> 3;               // 0 .. B*L-1   (8 chunks/row)
        const int jbase = (c & 7) * JCHUNK;
        const int b     = row / LSEQ;
        const int i     = row - b * LSEQ;
        const int boff  = b * LSEQ;
        const int ri    = rj[boff + i];
        const bool mi   = (mj[boff + i] != 0);

        float4* orow = reinterpret_cast<float4*>(out)
                     + (size_t)row * LSEQ * (CZ / 4);

        // 96 j's / 8 warps = 12 iterations per warp
        #pragma unroll 2
        for (int t = warp; t < JCHUNK; t += TPB / 32) {
            const int j = jbase + t;
            int d = rj[boff + j] - ri;
            d = min(max(d, -BINS), BINS) + BINS + 1;      // [1, 65]
            if (!(mi && (mj[boff + j] != 0))) d = 0;      // masked -> zero row
            float4 v = *reinterpret_cast<const float4*>(&wb[d * CZ + lane * 4]);
            __stcs(&orow[(size_t)j * (CZ / 4) + lane], v);
        }
    }
}

extern "C" void kernel_launch(void* const* d_in, const int* in_sizes, int n_in,
                              void* d_out, int out_size) {
    const int*   ridx  = (const int*)d_in[0];
    const int*   rmask = (const int*)d_in[1];
    const float* W     = (const float*)d_in[2];
    const float* bias  = (const float*)d_in[3];
    float*       out   = (float*)d_out;

    relpos_kernel<<<NCTAS, TPB>>>(ridx, rmask, W, bias, out);
}